// round 4
// baseline (speedup 1.0000x reference)
#include <cuda_runtime.h>
#include <math.h>

#define N_IMG   512
#define N_ANG   25
#define N_DET   512
#define N_SAMP  1024
#define N_RAYS  (N_ANG * N_DET)

#define SRC_DIST 512.0f
#define DET_DIST 512.0f
#define DET_SPACING 3.0f

// pair tables: g_pairs[g*512+f]  = (img[g][f],  img[g][f+1])   (row-major: g=row, f=col)
//              g_pairsT[g*512+f] = (img[f][g],  img[f+1][g])   (col-major: g=col, f=row)
__device__ float2 g_pairs [N_IMG * N_IMG];
__device__ float2 g_pairsT[N_IMG * N_IMG];

// one 32x32 tile per block; loads 33x33 halo tile, emits both pair arrays
__global__ __launch_bounds__(256)
void prep_kernel(const float* __restrict__ img) {
    __shared__ float tile[33][34];   // [r 0..32][c 0..32], padded
    int bx = blockIdx.x * 32;        // col base
    int by = blockIdx.y * 32;        // row base
    int tx = threadIdx.x;            // 0..31
    int ty = threadIdx.y;            // 0..7

    // load rows by..by+32, cols bx..bx+32 (zero-pad outside image)
    for (int r = ty; r < 33; r += 8) {
        int gr = by + r;
        bool rok = gr < N_IMG;
        tile[r][tx] = (rok) ? img[gr * N_IMG + bx + tx] : 0.0f;
        if (tx == 0) {
            int gc = bx + 32;
            tile[r][32] = (rok && gc < N_IMG) ? img[gr * N_IMG + gc] : 0.0f;
        }
    }
    __syncthreads();

    // row-major pairs: coalesced over tx = col
    #pragma unroll
    for (int r = ty; r < 32; r += 8)
        g_pairs[(by + r) * N_IMG + bx + tx] = make_float2(tile[r][tx], tile[r][tx + 1]);

    // col-major pairs: output index (bx+c)*512 + (by+r); coalesce over tx = r
    #pragma unroll
    for (int cc = ty; cc < 32; cc += 8)
        g_pairsT[(bx + cc) * N_IMG + by + tx] = make_float2(tile[tx][cc], tile[tx + 1][cc]);
}

// shrink [u0,u1] so that p + u*v stays within [lo, hi]
__device__ __forceinline__ void clip_axis(float p, float v, float lo, float hi,
                                          float& u0, float& u1) {
    if (fabsf(v) < 1e-12f) {
        if (p < lo || p > hi) { u0 = 1e30f; u1 = -1e30f; }
    } else {
        float inv = 1.0f / v;
        float a = (lo - p) * inv;
        float b = (hi - p) * inv;
        float mn = fminf(a, b), mx = fmaxf(a, b);
        u0 = fmaxf(u0, mn);
        u1 = fminf(u1, mx);
    }
}

__device__ __forceinline__ float fetch_masked(const float* __restrict__ img, int r, int c) {
    bool ok = (r >= 0) & (r < N_IMG) & (c >= 0) & (c < N_IMG);
    int rr = min(max(r, 0), N_IMG - 1);
    int cc = min(max(c, 0), N_IMG - 1);
    float v = __ldg(img + rr * N_IMG + cc);
    return ok ? v : 0.0f;
}

__global__ __launch_bounds__(256)
void fanbeam_kernel(const float* __restrict__ img, float* __restrict__ out) {
    int gwarp = blockIdx.x * 8 + (threadIdx.x >> 5);
    int lane  = threadIdx.x & 31;

    int a = gwarp / N_DET;
    int d = gwarp - a * N_DET;

    float beta = (float)a * (2.0f * 3.14159265358979323846f / (float)N_ANG);
    float s, c;
    sincosf(beta, &s, &c);

    float t  = ((float)d - (float)(N_DET - 1) * 0.5f) * DET_SPACING;
    float sx = -SRC_DIST * s;
    float sy =  SRC_DIST * c;
    float ex = t * c + DET_DIST * s;
    float ey = t * s - DET_DIST * c;
    float dx = ex - sx;
    float dy = ey - sy;
    float seg = sqrtf(dx * dx + dy * dy);

    const float half  = (float)(N_IMG - 1) * 0.5f;   // 255.5
    const float inv_s = 1.0f / (float)N_SAMP;
    float cA = sx + half;          // col(u) = cA + u*dx
    float rA = half - sy;          // row(u) = rA - u*dy

    float dxs = dx * inv_s;
    float dys = -dy * inv_s;
    float cA0 = fmaf(0.5f, dxs, cA);   // col(i) = cA0 + i*dxs
    float rA0 = fmaf(0.5f, dys, rA);   // row(i) = rA0 + i*dys

    // pick orientation: fast axis = larger per-sample step (memory-contiguous pairs)
    bool swp = fabsf(dys) > fabsf(dxs);
    const float2* __restrict__ base2 = swp ? g_pairsT : g_pairs;
    float fA0 = swp ? rA0 : cA0;   // fast-axis start (pair index)
    float fds = swp ? dys : dxs;
    float gA0 = swp ? cA0 : rA0;   // slow-axis start (table row)
    float gds = swp ? dxs : dys;

    // outer clip: any sample that can contribute
    const float eps = 1e-3f;
    float u0 = 0.0f, u1 = 1.0f;
    clip_axis(cA,  dx, -1.0f - eps, (float)N_IMG + eps, u0, u1);
    clip_axis(rA, -dy, -1.0f - eps, (float)N_IMG + eps, u0, u1);

    // interior clip: all 4 texels guaranteed in-bounds
    float w0 = u0, w1 = u1;
    clip_axis(cA,  dx, 0.01f, 510.99f, w0, w1);
    clip_axis(rA, -dy, 0.01f, 510.99f, w0, w1);

    float acc = 0.0f;

    if (u0 <= u1) {
        int s0 = max(0, (int)floorf(u0 * (float)N_SAMP - 0.5f));
        int s1 = min(N_SAMP - 1, (int)ceilf(u1 * (float)N_SAMP - 0.5f));

        int iA, iB;
        if (w0 <= w1) {
            iA = max(s0, (int)ceilf (w0 * (float)N_SAMP - 0.5f));
            iB = min(s1, (int)floorf(w1 * (float)N_SAMP - 0.5f));
            if (iA > iB) { iA = s1 + 1; iB = s1; }
        } else {
            iA = s1 + 1;
            iB = s1;
        }

        // ---- masked prefix: [s0, iA)  (original img, row/col semantics) ----
        for (int i = s0 + lane; i < iA; i += 32) {
            float fi  = (float)i;
            float col = fmaf(fi, dxs, cA0);
            float row = fmaf(fi, dys, rA0);
            int r0 = __float2int_rd(row);
            int c0 = __float2int_rd(col);
            float fr = row - (float)r0;
            float fc = col - (float)c0;
            float v00 = fetch_masked(img, r0,     c0);
            float v01 = fetch_masked(img, r0,     c0 + 1);
            float v10 = fetch_masked(img, r0 + 1, c0);
            float v11 = fetch_masked(img, r0 + 1, c0 + 1);
            float top = fmaf(fc, v01 - v00, v00);
            float bot = fmaf(fc, v11 - v10, v10);
            acc      += fmaf(fr, bot - top, top);
        }

        // ---- fast interior: [iA, iB], 2x LDG.64 per sample ----
        #pragma unroll 4
        for (int i = iA + lane; i <= iB; i += 32) {
            float fi = (float)i;
            float fp = fmaf(fi, fds, fA0);
            float gp = fmaf(fi, gds, gA0);
            int f0 = __float2int_rd(fp);
            int g0 = __float2int_rd(gp);
            float wf = fp - (float)f0;
            float wg = gp - (float)g0;
            const float2* p = base2 + (g0 << 9) + f0;
            float2 va = __ldg(p);            // (v[g0][f0],   v[g0][f0+1])
            float2 vb = __ldg(p + N_IMG);    // (v[g0+1][f0], v[g0+1][f0+1])
            float top = fmaf(wf, va.y - va.x, va.x);
            float bot = fmaf(wf, vb.y - vb.x, vb.x);
            acc      += fmaf(wg, bot - top, top);
        }

        // ---- masked suffix: (iB, s1] ----
        for (int i = iB + 1 + lane; i <= s1; i += 32) {
            float fi  = (float)i;
            float col = fmaf(fi, dxs, cA0);
            float row = fmaf(fi, dys, rA0);
            int r0 = __float2int_rd(row);
            int c0 = __float2int_rd(col);
            float fr = row - (float)r0;
            float fc = col - (float)c0;
            float v00 = fetch_masked(img, r0,     c0);
            float v01 = fetch_masked(img, r0,     c0 + 1);
            float v10 = fetch_masked(img, r0 + 1, c0);
            float v11 = fetch_masked(img, r0 + 1, c0 + 1);
            float top = fmaf(fc, v01 - v00, v00);
            float bot = fmaf(fc, v11 - v10, v10);
            acc      += fmaf(fr, bot - top, top);
        }
    }

    #pragma unroll
    for (int o = 16; o > 0; o >>= 1)
        acc += __shfl_down_sync(0xffffffffu, acc, o);

    if (lane == 0)
        out[gwarp] = acc * seg * inv_s;
}

extern "C" void kernel_launch(void* const* d_in, const int* in_sizes, int n_in,
                              void* d_out, int out_size) {
    (void)in_sizes; (void)n_in; (void)out_size;
    const float* img = (const float*)d_in[0];
    float* out = (float*)d_out;

    dim3 tb(32, 8);
    dim3 tg(N_IMG / 32, N_IMG / 32);
    prep_kernel<<<tg, tb>>>(img);

    fanbeam_kernel<<<N_RAYS / 8, 256>>>(img, out);
}